// round 3
// baseline (speedup 1.0000x reference)
#include <cuda_runtime.h>
#include <math.h>

#define DM   128
#define NH   8
#define HD   16
#define KTOT 164          // 9 + 25 + 49 + 81
#define PER_B 21504       // 128*128 + 64*64 + 32*32
#define MAXN 2048
#define MAXROWS (2*PER_B + MAXN*9)

// ---------------- device scratch ----------------
__device__ float g_x  [MAXN*DM];
__device__ float g_h  [MAXN*DM];
__device__ float g_q  [MAXN*DM];
__device__ float g_o  [MAXN*DM];
__device__ float g_t  [MAXN*512];
__device__ float g_qcs[MAXN*16];
__device__ float g_kcs[(size_t)MAXN*KTOT*16];
__device__ int   g_kidx[MAXN*KTOT];
__device__ int   g_kval[MAXN*KTOT];
__device__ int   g_rowsrc[MAXROWS];
__device__ float g_Kc[(size_t)MAXROWS*DM];
__device__ float g_Vc[(size_t)MAXROWS*DM];

__device__ __constant__ float c_invfreq[4] = {1.0f, 0.56234132519f, 0.316227766017f, 0.177827941004f};

__device__ __forceinline__ float gelu_tanh(float v) {
    float u = 0.7978845608028654f * (v + 0.044715f * v * v * v);
    return 0.5f * v * (1.f + tanhf(u));
}

__device__ __forceinline__ int batch_of(int q, const int* qbo, int n_off) {
    int b = 0;
    for (int t = 1; t < n_off - 1; t++) if (q >= qbo[t]) b = t;
    return b;
}

// ---------------- precompute ----------------
__global__ void copy_x_kernel(const float* __restrict__ src, int n) {
    int i = blockIdx.x * blockDim.x + threadIdx.x;
    if (i < n) g_x[i] = src[i];
}

__global__ void build_rowsrc_kernel(const float* __restrict__ qpos,
                                    const int* __restrict__ qbo, int n_off,
                                    int R123, int R) {
    int e = blockIdx.x * blockDim.x + threadIdx.x;
    if (e >= R) return;
    int src;
    if (e < R123) {
        int b = e / PER_B, r = e % PER_B;
        int l, i, j;
        if (r < 16384)      { l = 1; i = r >> 7; j = r & 127; }
        else if (r < 20480) { int rr = r - 16384; l = 2; i = rr >> 6; j = rr & 63; }
        else                { int rr = r - 20480; l = 3; i = rr >> 5; j = rr & 31; }
        src = ((b * 256 + (i << (8 - l))) ) ; // placeholder avoided; compute directly below
        src = ((b * 256 + i) * 256 + j) * 4 + l;
        // NOTE: dense rows use the level's own (i,j); fm layout is [b,256,256,4,128]
        // but levels 1..3 only occupy i<Hl, j<Wl — we index fm[b, i, j, l] directly.
    } else {
        int e2 = e - R123;
        int q = e2 / 9, t = e2 % 9;
        int b = batch_of(q, qbo, n_off);
        float p0 = qpos[2*q], p1 = qpos[2*q+1];
        int c0 = (int)floorf(p0), c1 = (int)floorf(p1);
        int gi = c0 + t / 3 - 1, gj = c1 + t % 3 - 1;
        gi = min(max(gi, 0), 255); gj = min(max(gj, 0), 255);
        src = ((b * 256 + gi) * 256 + gj) * 4 + 0;
    }
    g_rowsrc[e] = src;
}

__global__ void build_keys_kernel(const float* __restrict__ qpos,
                                  const int* __restrict__ qbo, int n_off,
                                  const int* __restrict__ shapes,
                                  int N, int R123) {
    int id = blockIdx.x * blockDim.x + threadIdx.x;
    if (id >= N * KTOT) return;
    int q = id / KTOT, k = id % KTOT;
    int l, t, d;
    if      (k < 9)  { l = 0; t = k;      d = 3; }
    else if (k < 34) { l = 1; t = k - 9;  d = 5; }
    else if (k < 83) { l = 2; t = k - 34; d = 7; }
    else             { l = 3; t = k - 83; d = 9; }
    int Hl = shapes[2*l], Wl = shapes[2*l+1];
    float sh = (float)Hl / (float)shapes[0];
    float sw = (float)Wl / (float)shapes[1];
    float p0 = qpos[2*q], p1 = qpos[2*q+1];
    int c0 = (int)floorf(p0 * sh), c1 = (int)floorf(p1 * sw);
    int gi = c0 + t / d - d / 2;
    int gj = c1 + t % d - d / 2;
    int valid = (gi >= 0 && gi < Hl && gj >= 0 && gj < Wl);
    int ci = min(max(gi, 0), Hl - 1), cj = min(max(gj, 0), Wl - 1);
    int b = batch_of(q, qbo, n_off);
    int idx;
    if (l == 0) idx = R123 + q * 9 + t;
    else {
        int base = (l == 1) ? 0 : (l == 2) ? 16384 : 20480;
        idx = b * PER_B + base + ci * Wl + cj;
    }
    g_kidx[id] = idx;
    g_kval[id] = valid;
    float kp0 = ((float)gi + 0.5f) / sh;
    float kp1 = ((float)gj + 0.5f) / sw;
    float* cs = &g_kcs[(size_t)id * 16];
    #pragma unroll
    for (int f = 0; f < 4; f++) {
        float a0 = kp0 * c_invfreq[f];
        float a1 = kp1 * c_invfreq[f];
        cs[f]      = cosf(a0);  cs[8  + f] = sinf(a0);
        cs[4 + f]  = cosf(a1);  cs[12 + f] = sinf(a1);
    }
}

__global__ void build_qcs_kernel(const float* __restrict__ qpos, int N) {
    int q = blockIdx.x * blockDim.x + threadIdx.x;
    if (q >= N) return;
    float p0 = qpos[2*q], p1 = qpos[2*q+1];
    float* cs = &g_qcs[q * 16];
    #pragma unroll
    for (int f = 0; f < 4; f++) {
        float a0 = p0 * c_invfreq[f];
        float a1 = p1 * c_invfreq[f];
        cs[f]      = cosf(a0);  cs[8  + f] = sinf(a0);
        cs[4 + f]  = cosf(a1);  cs[12 + f] = sinf(a1);
    }
}

// ---------------- per-layer kernels ----------------
__global__ void ln_qproj_kernel(const float* __restrict__ lg, const float* __restrict__ lb,
                                const float* __restrict__ Wq) {
    int q = blockIdx.x, tid = threadIdx.x;
    int lane = tid & 31, w = tid >> 5;
    __shared__ float sh[128];
    __shared__ float sraw[128];
    __shared__ float red[8];
    float x = g_x[q*DM + tid];
    float s1 = x, s2 = x * x;
    #pragma unroll
    for (int o = 16; o; o >>= 1) {
        s1 += __shfl_xor_sync(0xffffffffu, s1, o);
        s2 += __shfl_xor_sync(0xffffffffu, s2, o);
    }
    if (lane == 0) { red[w] = s1; red[4 + w] = s2; }
    __syncthreads();
    float mean = (red[0] + red[1] + red[2] + red[3]) * (1.f / 128.f);
    float var  = (red[4] + red[5] + red[6] + red[7]) * (1.f / 128.f) - mean * mean;
    float hval = (x - mean) * rsqrtf(var + 1e-5f) * lg[tid] + lb[tid];
    sh[tid] = hval;
    __syncthreads();
    float acc = 0.f;
    #pragma unroll 8
    for (int i = 0; i < 128; i++) acc += sh[i] * Wq[i * DM + tid];
    sraw[tid] = acc;
    __syncthreads();
    int p = (tid >> 1) & 7;
    float c = g_qcs[q*16 + p], s = g_qcs[q*16 + 8 + p];
    float x1 = sraw[tid & ~1];
    float x2 = sraw[tid |  1];
    g_q[q*DM + tid] = (tid & 1) ? (x1 * s + x2 * c) : (x1 * c - x2 * s);
}

__global__ void __launch_bounds__(256)
kvproj_kernel(const float* __restrict__ fm, const float* __restrict__ Wk,
              const float* __restrict__ Wv, int R) {
    __shared__ float sF[64][33];
    __shared__ float sWk[32][128];
    __shared__ float sWv[32][128];
    int tid = threadIdx.x;
    int cc = tid & 31, rr = tid >> 5;
    int row0 = blockIdx.x * 64;
    float aK[8][4], aV[8][4];
    #pragma unroll
    for (int u = 0; u < 8; u++)
        #pragma unroll
        for (int v = 0; v < 4; v++) { aK[u][v] = 0.f; aV[u][v] = 0.f; }

    for (int kt = 0; kt < 4; kt++) {
        __syncthreads();
        for (int fi = tid; fi < 512; fi += 256) {
            int r = fi >> 3, c4 = fi & 7;
            int row = row0 + r; if (row >= R) row = R - 1;
            int src = g_rowsrc[row];
            float4 v = *(const float4*)(fm + (size_t)src * 128 + kt * 32 + c4 * 4);
            sF[r][c4*4+0] = v.x; sF[r][c4*4+1] = v.y;
            sF[r][c4*4+2] = v.z; sF[r][c4*4+3] = v.w;
        }
        for (int wi = tid; wi < 1024; wi += 256) {
            int r = wi >> 5, c4 = wi & 31;
            *(float4*)&sWk[r][c4*4] = *(const float4*)(Wk + (kt*32 + r) * 128 + c4 * 4);
            *(float4*)&sWv[r][c4*4] = *(const float4*)(Wv + (kt*32 + r) * 128 + c4 * 4);
        }
        __syncthreads();
        #pragma unroll 4
        for (int kk = 0; kk < 32; kk++) {
            float f[8];
            #pragma unroll
            for (int u = 0; u < 8; u++) f[u] = sF[rr*8 + u][kk];
            float4 wk4 = *(const float4*)&sWk[kk][cc*4];
            float4 wv4 = *(const float4*)&sWv[kk][cc*4];
            #pragma unroll
            for (int u = 0; u < 8; u++) {
                aK[u][0] += f[u]*wk4.x; aK[u][1] += f[u]*wk4.y;
                aK[u][2] += f[u]*wk4.z; aK[u][3] += f[u]*wk4.w;
                aV[u][0] += f[u]*wv4.x; aV[u][1] += f[u]*wv4.y;
                aV[u][2] += f[u]*wv4.z; aV[u][3] += f[u]*wv4.w;
            }
        }
    }
    #pragma unroll
    for (int u = 0; u < 8; u++) {
        int row = row0 + rr*8 + u;
        if (row < R) {
            *(float4*)&g_Kc[(size_t)row*128 + cc*4] = make_float4(aK[u][0], aK[u][1], aK[u][2], aK[u][3]);
            *(float4*)&g_Vc[(size_t)row*128 + cc*4] = make_float4(aV[u][0], aV[u][1], aV[u][2], aV[u][3]);
        }
    }
}

__global__ void attn_kernel() {
    int q = blockIdx.x, tid = threadIdx.x;
    int lane = tid & 31, w = tid >> 5;
    __shared__ float sq[128];
    __shared__ float ssc[8 * KTOT];
    __shared__ int   skidx[KTOT];
    sq[tid] = g_q[q*DM + tid];
    for (int k = tid; k < KTOT; k += 128) skidx[k] = g_kidx[q*KTOT + k];
    __syncthreads();
    float4 qv = *(const float4*)&sq[lane * 4];
    for (int k = w; k < KTOT; k += 4) {
        int idx = skidx[k];
        float4 kv = *(const float4*)&g_Kc[(size_t)idx*DM + lane*4];
        const float* cs = &g_kcs[(size_t)((size_t)q*KTOT + k) * 16];
        float csv = (lane < 16) ? cs[lane] : 0.f;
        int m = lane & 3;
        float c0 = __shfl_sync(0xffffffffu, csv, 2*m);
        float s0 = __shfl_sync(0xffffffffu, csv, 8 + 2*m);
        float c1 = __shfl_sync(0xffffffffu, csv, 2*m + 1);
        float s1 = __shfl_sync(0xffffffffu, csv, 9 + 2*m);
        float r0 = kv.x*c0 - kv.y*s0;
        float r1 = kv.x*s0 + kv.y*c0;
        float r2 = kv.z*c1 - kv.w*s1;
        float r3 = kv.z*s1 + kv.w*c1;
        float ps = r0*qv.x + r1*qv.y + r2*qv.z + r3*qv.w;
        ps += __shfl_xor_sync(0xffffffffu, ps, 1);
        ps += __shfl_xor_sync(0xffffffffu, ps, 2);
        if ((lane & 3) == 0) {
            int h = lane >> 2;
            int val = g_kval[q*KTOT + k];
            ssc[h*KTOT + k] = val ? ps * 0.25f : -1.0e9f;
        }
    }
    __syncthreads();
    #pragma unroll
    for (int hh = 0; hh < 2; hh++) {
        int h = w * 2 + hh;
        float mx = -3.0e38f;
        for (int k = lane; k < KTOT; k += 32) mx = fmaxf(mx, ssc[h*KTOT + k]);
        #pragma unroll
        for (int o = 16; o; o >>= 1) mx = fmaxf(mx, __shfl_xor_sync(0xffffffffu, mx, o));
        float sum = 0.f;
        for (int k = lane; k < KTOT; k += 32) {
            float e = expf(ssc[h*KTOT + k] - mx);
            ssc[h*KTOT + k] = e;
            sum += e;
        }
        #pragma unroll
        for (int o = 16; o; o >>= 1) sum += __shfl_xor_sync(0xffffffffu, sum, o);
        float inv = 1.f / sum;
        for (int k = lane; k < KTOT; k += 32) ssc[h*KTOT + k] *= inv;
    }
    __syncthreads();
    int h = tid >> 4;
    float acc = 0.f;
    #pragma unroll 4
    for (int k = 0; k < KTOT; k++)
        acc += ssc[h*KTOT + k] * g_Vc[(size_t)skidx[k]*DM + tid];
    g_o[q*DM + tid] = acc;
}

__global__ void oproj_ln2_kernel(const float* __restrict__ Wo,
                                 const float* __restrict__ lg, const float* __restrict__ lb) {
    int q = blockIdx.x, tid = threadIdx.x;
    int lane = tid & 31, w = tid >> 5;
    __shared__ float so[128];
    __shared__ float red[8];
    so[tid] = g_o[q*DM + tid];
    __syncthreads();
    float acc = 0.f;
    #pragma unroll 8
    for (int i = 0; i < 128; i++) acc += so[i] * Wo[i * DM + tid];
    float x = g_x[q*DM + tid] + acc;
    g_x[q*DM + tid] = x;
    float s1 = x, s2 = x * x;
    #pragma unroll
    for (int o = 16; o; o >>= 1) {
        s1 += __shfl_xor_sync(0xffffffffu, s1, o);
        s2 += __shfl_xor_sync(0xffffffffu, s2, o);
    }
    if (lane == 0) { red[w] = s1; red[4 + w] = s2; }
    __syncthreads();
    float mean = (red[0] + red[1] + red[2] + red[3]) * (1.f / 128.f);
    float var  = (red[4] + red[5] + red[6] + red[7]) * (1.f / 128.f) - mean * mean;
    g_h[q*DM + tid] = (x - mean) * rsqrtf(var + 1e-5f) * lg[tid] + lb[tid];
}

__global__ void ffn1_kernel(const float* __restrict__ W1, const float* __restrict__ pb, int N) {
    int q0 = blockIdx.x * 8, tid = threadIdx.x;
    __shared__ float sh2[8][128];
    for (int i = tid; i < 1024; i += 256) {
        int r = i >> 7, c = i & 127;
        int q = q0 + r;
        sh2[r][c] = (q < N) ? g_h[q*DM + c] : 0.f;
    }
    __syncthreads();
    float acc[8][2];
    #pragma unroll
    for (int r = 0; r < 8; r++) { acc[r][0] = 0.f; acc[r][1] = 0.f; }
    #pragma unroll 4
    for (int i = 0; i < 128; i++) {
        float w0 = W1[i*512 + tid];
        float w1 = W1[i*512 + 256 + tid];
        #pragma unroll
        for (int r = 0; r < 8; r++) {
            float hv = sh2[r][i];
            acc[r][0] += hv * w0;
            acc[r][1] += hv * w1;
        }
    }
    float bb0 = pb[tid], bb1 = pb[256 + tid];
    #pragma unroll
    for (int r = 0; r < 8; r++) {
        int q = q0 + r;
        if (q < N) {
            g_t[q*512 + tid]       = gelu_tanh(acc[r][0] + bb0);
            g_t[q*512 + 256 + tid] = gelu_tanh(acc[r][1] + bb1);
        }
    }
}

__global__ void ffn2_kernel(const float* __restrict__ W2, const float* __restrict__ pb, int N) {
    int q0 = blockIdx.x * 8, tid = threadIdx.x;
    __shared__ float st[8][512];
    for (int i = tid; i < 4096; i += 128) {
        int r = i >> 9, c = i & 511;
        int q = q0 + r;
        st[r][c] = (q < N) ? g_t[q*512 + c] : 0.f;
    }
    __syncthreads();
    float acc[8];
    #pragma unroll
    for (int r = 0; r < 8; r++) acc[r] = 0.f;
    #pragma unroll 4
    for (int i = 0; i < 512; i++) {
        float wv = W2[i*128 + tid];
        #pragma unroll
        for (int r = 0; r < 8; r++) acc[r] += st[r][i] * wv;
    }
    float bb = pb[tid];
    #pragma unroll
    for (int r = 0; r < 8; r++) {
        int q = q0 + r;
        if (q < N) g_x[q*DM + tid] += acc[r] + bb;
    }
}

__global__ void logits_kernel(const float* __restrict__ fm, const float* __restrict__ qpos,
                              const int* __restrict__ qbo, int n_off,
                              const int* __restrict__ shapes, float* __restrict__ out) {
    int q = blockIdx.x, tid = threadIdx.x;
    int lane = tid & 31, w = tid >> 5;
    __shared__ float sx[128];
    __shared__ int sb;
    if (tid < 128) sx[tid] = g_x[q*DM + tid];
    if (tid == 0) sb = batch_of(q, qbo, n_off);
    __syncthreads();
    int H0 = shapes[0], W0 = shapes[1];
    float p0 = qpos[2*q], p1 = qpos[2*q+1];
    int c0 = (int)floorf(p0), c1 = (int)floorf(p1);
    float4 xv = *(const float4*)&sx[lane * 4];
    int b = sb;
    for (int pp = w; pp < 49; pp += 8) {
        int gi = c0 + pp / 7 - 3;
        int gj = c1 + pp % 7 - 3;
        bool valid = (gi >= 0 && gi < H0 && gj >= 0 && gj < W0);
        int ci = min(max(gi, 0), H0 - 1), cj = min(max(gj, 0), W0 - 1);
        const float* f = fm + ((((size_t)b * 256 + ci) * 256 + cj) * 4 + 0) * 128;
        float4 fv = *(const float4*)(f + lane * 4);
        float d = fv.x*xv.x + fv.y*xv.y + fv.z*xv.z + fv.w*xv.w;
        #pragma unroll
        for (int o = 16; o; o >>= 1) d += __shfl_xor_sync(0xffffffffu, d, o);
        if (lane == 0) out[q*49 + pp] = valid ? d : 0.f;
    }
}

// ---------------- launch ----------------
extern "C" void kernel_launch(void* const* d_in, const int* in_sizes, int n_in,
                              void* d_out, int out_size) {
    const float* queries = (const float*)d_in[0];
    const int*   qbo     = (const int*)  d_in[1];
    const float* qpos    = (const float*)d_in[2];
    const float* fm      = (const float*)d_in[3];
    const int*   shapes  = (const int*)  d_in[4];
    const float* Wq      = (const float*)d_in[5];
    const float* Wk      = (const float*)d_in[6];
    const float* Wv      = (const float*)d_in[7];
    const float* Wo      = (const float*)d_in[8];
    const float* ln1g    = (const float*)d_in[9];
    const float* ln1b    = (const float*)d_in[10];
    const float* ln2g    = (const float*)d_in[11];
    const float* ln2b    = (const float*)d_in[12];
    const float* W1      = (const float*)d_in[13];
    const float* b1      = (const float*)d_in[14];
    const float* W2      = (const float*)d_in[15];
    const float* b2      = (const float*)d_in[16];

    int N     = in_sizes[0] / DM;
    int n_off = in_sizes[1];
    int B     = in_sizes[3] / (256 * 256 * 4 * DM);
    int nl    = in_sizes[5] / (DM * DM);
    int R123  = B * PER_B;
    int R     = R123 + N * 9;

    copy_x_kernel<<<(N*DM + 255) / 256, 256>>>(queries, N * DM);
    build_rowsrc_kernel<<<(R + 255) / 256, 256>>>(qpos, qbo, n_off, R123, R);
    build_keys_kernel<<<(N*KTOT + 127) / 128, 128>>>(qpos, qbo, n_off, shapes, N, R123);
    build_qcs_kernel<<<(N + 127) / 128, 128>>>(qpos, N);

    for (int li = 0; li < nl; li++) {
        ln_qproj_kernel<<<N, 128>>>(ln1g + li*DM, ln1b + li*DM, Wq + li*DM*DM);
        kvproj_kernel<<<(R + 63) / 64, 256>>>(fm, Wk + li*DM*DM, Wv + li*DM*DM, R);
        attn_kernel<<<N, 128>>>();
        oproj_ln2_kernel<<<N, 128>>>(Wo + li*DM*DM, ln2g + li*DM, ln2b + li*DM);
        ffn1_kernel<<<(N + 7) / 8, 256>>>(W1 + li*DM*512, b1 + li*512, N);
        ffn2_kernel<<<(N + 7) / 8, 128>>>(W2 + li*512*DM, b2 + li*DM, N);
    }
    logits_kernel<<<N, 256>>>(fm, qpos, qbo, n_off, shapes, (float*)d_out);
}